// round 15
// baseline (speedup 1.0000x reference)
#include <cuda_runtime.h>
#include <math.h>

#define NL 51
#define LS 53
#define STARTI 51
#define ENDI 52
#define LOG2E 1.4426950408889634f
#define LN2   0.6931471805599453f

typedef unsigned long long ull;

__device__ __forceinline__ ull f2pack(float lo, float hi) {
    ull u;
    asm("mov.b64 %0, {%1, %2};" : "=l"(u) : "f"(lo), "f"(hi));
    return u;
}
__device__ __forceinline__ void f2fma(ull& d, ull a, ull b) {
    asm("fma.rn.f32x2 %0, %1, %2, %0;" : "+l"(d) : "l"(a), "l"(b));
}
__device__ __forceinline__ ull f2add(ull a, ull b) {
    ull d;
    asm("add.rn.f32x2 %0, %1, %2;" : "=l"(d) : "l"(a), "l"(b));
    return d;
}
__device__ __forceinline__ float2 f2unpack(ull u) {
    float lo, hi;
    asm("mov.b64 {%0, %1}, %2;" : "=f"(lo), "=f"(hi) : "l"(u));
    return make_float2(lo, hi);
}
__device__ __forceinline__ float ex2_approx(float x) {
    float r;
    asm("ex2.approx.f32 %0, %1;" : "=f"(r) : "f"(x));
    return r;
}

// ---------------------------------------------------------------------------
// Gold score (separate, cheap, fully parallel)
// ---------------------------------------------------------------------------
__global__ void crf_gold(const float* __restrict__ logits,
                         const int* __restrict__ labels,
                         const int* __restrict__ lens,
                         const float* __restrict__ T,
                         float* __restrict__ out, int S)
{
    __shared__ float sT[LS * LS];
    __shared__ float red[8];
    int b = blockIdx.x, tid = threadIdx.x;
    for (int i = tid; i < LS * LS; i += blockDim.x) sT[i] = T[i];
    __syncthreads();

    int len = lens[b];
    if (len < 1) len = 1;
    if (len > S) len = S;

    const int*   lab = labels + (size_t)b * S;
    const float* lg  = logits + (size_t)b * S * NL;

    float s = 0.f;
    for (int j = tid; j <= len; j += 256) {
        int from = (j == 0)   ? STARTI : lab[j - 1];
        int to   = (j == len) ? ENDI   : lab[j];
        s += sT[to * LS + from];
        if (j < len) s += lg[(size_t)j * NL + to];
    }
    #pragma unroll
    for (int o = 16; o; o >>= 1) s += __shfl_xor_sync(0xffffffffu, s, o);
    if ((tid & 31) == 0) red[tid >> 5] = s;
    __syncthreads();
    if (tid == 0) {
        float v = 0.f;
        #pragma unroll
        for (int i = 0; i < 8; i++) v += red[i];
        out[b] += v;            // crf_fwd has already written -norm
    }
}

// ---------------------------------------------------------------------------
// Forward recursion: DEDICATED kernel (fusion makes ptxas spill E — R5/R11).
// One warp per chain, branchless loop, permuted layout
// (lane l -> slots 2l = B-Tl, 2l+1 = I-Tl; lane 25 = O; lane 26 = START).
// Per-step __syncwarp is load-bearing (STS drain; R8/R9).
// Per-step tokens FROZEN at the R6/R14 layout; only the loop skeleton is
// unrolled 4x (loop-overhead amortization + cross-step LDG hoisting room).
// ---------------------------------------------------------------------------
__global__ void __launch_bounds__(64) crf_fwd(const float* __restrict__ logits,
                                              const int* __restrict__ lens,
                                              const float* __restrict__ T,
                                              float* __restrict__ out, int S)
{
    __shared__ __align__(16) float shw[2][2][64];   // [warp][buf][64]

    const int warp = threadIdx.x >> 5;
    const int lane = threadIdx.x & 31;
    const int b    = blockIdx.x * 2 + warp;

    int len = lens[b];
    if (len < 1) len = 1;
    if (len > S) len = S;
    const int lenm1 = len - 1;

    const float* lg = logits + (size_t)b * S * NL;

    // ---- lane roles ----
    const int   st_e = (lane <= 24) ? (2 * lane + 1) : (lane == 25 ? 0 : STARTI);
    const int   st_o = (lane <= 24) ? (2 * lane + 2) : 0;
    const int   dld  = (st_e < NL) ? st_e : 0;      // clamped logit index
    const int   sld  = st_o;
    const float cD   = (lane == 26) ? 0.f : LOG2E;  // START: G = 2^0 = 1

    // ---- E row (permuted columns) + constants ----
    ull   E[28];
    float TmaxL2d, TmaxL2s;
    {
        const float* row = T + st_e * LS;
        float m = row[0];
        #pragma unroll
        for (int f = 1; f < LS; f++) m = fmaxf(m, row[f]);
        #pragma unroll
        for (int p = 0; p < 28; p++) {
            int se = (p <= 24) ? (2 * p + 1) : (p == 25 ? 0 : (p == 26 ? STARTI : -1));
            int so = (p <= 24) ? (2 * p + 2) : -1;
            float a = (se >= 0) ? __expf(row[se] - m) : 0.f;
            float c = (so >= 0) ? __expf(row[so] - m) : 0.f;
            E[p] = f2pack(a, c);
        }
        TmaxL2d = (lane <= 25) ? m * LOG2E
                : (lane == 26) ? 0.f : -INFINITY;   // pads: GD = 0 exactly
        TmaxL2s = (lane <= 24) ? T[st_o * LS + st_e] * LOG2E : -INFINITY;
    }

    // ---- init state ----
    float* buf0 = &shw[warp][0][0];
    float* buf1 = &shw[warp][1][0];
    #pragma unroll
    for (int i = lane; i < 128; i += 32) buf0[i] = 0.f;
    if (lane == 26) buf0[52] = 1.f;                 // w0 = e_START
    float wn_prev  = (lane == 26) ? 1.f : 0.f;
    float wns_prev = 0.f;

    // ---- 3-deep clamped prefetch ----
    float gd0, gd1, gd2, gs0, gs1, gs2;
    {
        int i1 = min(1, lenm1), i2 = min(2, lenm1);
        gd0 = lg[dld];
        gs0 = lg[sld];
        gd1 = lg[(size_t)i1 * NL + dld];
        gs1 = lg[(size_t)i1 * NL + sld];
        gd2 = lg[(size_t)i2 * NL + dld];
        gs2 = lg[(size_t)i2 * NL + sld];
    }

    int A = 0;   // raw exponent-bit accumulator
    __syncwarp();

#define CRF_STEP(WIN, WOUT, T_CUR)                                            \
    {                                                                         \
        const ulonglong2* wv = reinterpret_cast<const ulonglong2*>(WIN);      \
        ulonglong2 v13 = wv[13];    /* slots 52..55 first: scale path */      \
        unsigned bits = __float_as_uint(f2unpack(v13.x).x);                   \
        float scale = __int_as_float(0x7F000000u - (bits & 0x7F800000u));     \
        A += (int)(bits >> 23);                                               \
        float GD = ex2_approx(__fmaf_rn(gd0, cD,    TmaxL2d)) * scale;        \
        float GS = ex2_approx(__fmaf_rn(gs0, LOG2E, TmaxL2s)) * scale;        \
        float wns = GS * wn_prev;                                             \
        ulonglong2 v[13];                                                     \
        _Pragma("unroll")                                                     \
        for (int j = 0; j < 13; j++) v[j] = wv[j];                            \
        ull a0 = 0, a1 = 0, a2 = 0, a3 = 0;                                   \
        _Pragma("unroll")                                                     \
        for (int j = 0; j < 12; j += 2) {                                     \
            f2fma(a0, E[2 * j],     v[j].x);                                  \
            f2fma(a1, E[2 * j + 1], v[j].y);                                  \
            f2fma(a2, E[2 * j + 2], v[j + 1].x);                              \
            f2fma(a3, E[2 * j + 3], v[j + 1].y);                              \
        }                                                                     \
        f2fma(a0, E[24], v[12].x);                                            \
        f2fma(a1, E[25], v[12].y);                                            \
        f2fma(a2, E[26], v13.x);                                              \
        f2fma(a3, E[27], v13.y);                                              \
        float2 pp = f2unpack(f2add(f2add(a0, a1), f2add(a2, a3)));            \
        float wn = GD * (pp.x + pp.y);                                        \
        reinterpret_cast<float2*>(WOUT)[lane] = make_float2(wn, wns);         \
        wn_prev = wn; wns_prev = wns;                                         \
        gd0 = gd1; gd1 = gd2; gs0 = gs1; gs1 = gs2;                           \
        int tn = min((T_CUR) + 3, lenm1);                                     \
        const float* lgn = lg + (size_t)tn * NL;                              \
        gd2 = lgn[dld];                                                       \
        gs2 = lgn[sld];                                                       \
        __syncwarp();                                                         \
    }

    int t = 0;
    while (t + 4 <= len) {
        CRF_STEP(buf0, buf1, t);
        CRF_STEP(buf1, buf0, t + 1);
        CRF_STEP(buf0, buf1, t + 2);
        CRF_STEP(buf1, buf0, t + 3);
        t += 4;
    }
    while (t + 2 <= len) {
        CRF_STEP(buf0, buf1, t);
        CRF_STEP(buf1, buf0, t + 1);
        t += 2;
    }
    if (t < len) {
        CRF_STEP(buf0, buf1, t);
    }
#undef CRF_STEP

    // ---- END contraction from registers + warp reduce ----
    float cE_d = (lane <= 26) ? __expf(T[ENDI * LS + st_e] - 100.f) : 0.f;
    float cE_s = (lane <= 24) ? __expf(T[ENDI * LS + st_o] - 100.f) : 0.f;
    float dot = cE_d * wn_prev + cE_s * wns_prev;
    #pragma unroll
    for (int o = 16; o; o >>= 1) dot += __shfl_xor_sync(0xffffffffu, dot, o);
    if (lane == 0) {
        float norm = (float)(A - 127 * len) * LN2 + 100.f + __logf(dot);
        out[b] = -norm;          // crf_gold adds the gold score afterwards
    }
}

extern "C" void kernel_launch(void* const* d_in, const int* in_sizes, int n_in,
                              void* d_out, int out_size)
{
    const float* logits = (const float*)d_in[0];
    const int*   labels = (const int*)d_in[1];
    const int*   lens   = (const int*)d_in[2];
    const float* T      = (const float*)d_in[3];
    float*       out    = (float*)d_out;

    int B = out_size;                       // 256
    int S = in_sizes[1] / B;                // 2048

    crf_fwd <<<B / 2, 64>>>(logits, lens, T, out, S);
    crf_gold<<<B, 256>>>(logits, labels, lens, T, out, S);
}

// round 16
// speedup vs baseline: 1.3873x; 1.3873x over previous
#include <cuda_runtime.h>
#include <math.h>

#define NL 51
#define LS 53
#define STARTI 51
#define ENDI 52
#define LOG2E 1.4426950408889634f
#define LN2   0.6931471805599453f

typedef unsigned long long ull;

__device__ __forceinline__ ull f2pack(float lo, float hi) {
    ull u;
    asm("mov.b64 %0, {%1, %2};" : "=l"(u) : "f"(lo), "f"(hi));
    return u;
}
__device__ __forceinline__ void f2fma(ull& d, ull a, ull b) {
    asm("fma.rn.f32x2 %0, %1, %2, %0;" : "+l"(d) : "l"(a), "l"(b));
}
__device__ __forceinline__ ull f2add(ull a, ull b) {
    ull d;
    asm("add.rn.f32x2 %0, %1, %2;" : "=l"(d) : "l"(a), "l"(b));
    return d;
}
__device__ __forceinline__ float2 f2unpack(ull u) {
    float lo, hi;
    asm("mov.b64 {%0, %1}, %2;" : "=f"(lo), "=f"(hi) : "l"(u));
    return make_float2(lo, hi);
}
__device__ __forceinline__ float ex2_approx(float x) {
    float r;
    asm("ex2.approx.f32 %0, %1;" : "=f"(r) : "f"(x));
    return r;
}

// ---------------------------------------------------------------------------
// Gold score (separate, cheap, fully parallel)
// ---------------------------------------------------------------------------
__global__ void crf_gold(const float* __restrict__ logits,
                         const int* __restrict__ labels,
                         const int* __restrict__ lens,
                         const float* __restrict__ T,
                         float* __restrict__ out, int S)
{
    __shared__ float sT[LS * LS];
    __shared__ float red[8];
    int b = blockIdx.x, tid = threadIdx.x;
    for (int i = tid; i < LS * LS; i += blockDim.x) sT[i] = T[i];
    __syncthreads();

    int len = lens[b];
    if (len < 1) len = 1;
    if (len > S) len = S;

    const int*   lab = labels + (size_t)b * S;
    const float* lg  = logits + (size_t)b * S * NL;

    float s = 0.f;
    for (int j = tid; j <= len; j += 256) {
        int from = (j == 0)   ? STARTI : lab[j - 1];
        int to   = (j == len) ? ENDI   : lab[j];
        s += sT[to * LS + from];
        if (j < len) s += lg[(size_t)j * NL + to];
    }
    #pragma unroll
    for (int o = 16; o; o >>= 1) s += __shfl_xor_sync(0xffffffffu, s, o);
    if ((tid & 31) == 0) red[tid >> 5] = s;
    __syncthreads();
    if (tid == 0) {
        float v = 0.f;
        #pragma unroll
        for (int i = 0; i < 8; i++) v += red[i];
        out[b] += v;            // crf_fwd has already written -norm
    }
}

// ---------------------------------------------------------------------------
// Forward recursion: one warp per chain, branchless loop, permuted layout.
//   lane l<=24 : slot 2l = B-Tl,  slot 2l+1 = I-Tl (sparse src = own B-Tl reg)
//   lane 25    : slot 50 = O
//   lane 26    : slot 52 = START (G = 1); slot 52 value = Z_t (renorm source)
//   lanes >=27 : zeros (TmaxL2 = -INF -> ex2 = 0 exactly)
// Per-step __syncwarp is load-bearing (drains STS so broadcast LDS avoids
// store-hazard replays). Unroll-2 with static ping/pong buffers. This exact
// configuration is the measured local optimum (R6 = 293.9 us); all probed
// neighbors (no-sync, shfl, fusion, unroll-4, load-pattern changes) regress.
// ---------------------------------------------------------------------------
__global__ void __launch_bounds__(64) crf_fwd(const float* __restrict__ logits,
                                              const int* __restrict__ lens,
                                              const float* __restrict__ T,
                                              float* __restrict__ out, int S)
{
    __shared__ __align__(16) float shw[2][2][64];   // [warp][buf][64]

    const int warp = threadIdx.x >> 5;
    const int lane = threadIdx.x & 31;
    const int b    = blockIdx.x * 2 + warp;

    int len = lens[b];
    if (len < 1) len = 1;
    if (len > S) len = S;
    const int lenm1 = len - 1;

    const float* lg = logits + (size_t)b * S * NL;

    // ---- lane roles ----
    const int   st_e = (lane <= 24) ? (2 * lane + 1) : (lane == 25 ? 0 : STARTI);
    const int   st_o = (lane <= 24) ? (2 * lane + 2) : 0;
    const int   dld  = (st_e < NL) ? st_e : 0;      // clamped logit index
    const int   sld  = st_o;
    const float mD   = (lane == 26) ? 0.f : 1.f;    // START uses pad logit: G = 1

    // ---- E row (permuted columns) + constants ----
    ull   E[28];
    float TmaxL2d, TmaxL2s;
    {
        const float* row = T + st_e * LS;
        float m = row[0];
        #pragma unroll
        for (int f = 1; f < LS; f++) m = fmaxf(m, row[f]);
        #pragma unroll
        for (int p = 0; p < 28; p++) {
            int se = (p <= 24) ? (2 * p + 1) : (p == 25 ? 0 : (p == 26 ? STARTI : -1));
            int so = (p <= 24) ? (2 * p + 2) : -1;
            float a = (se >= 0) ? __expf(row[se] - m) : 0.f;
            float c = (so >= 0) ? __expf(row[so] - m) : 0.f;
            E[p] = f2pack(a, c);
        }
        TmaxL2d = (lane <= 25) ? m * LOG2E
                : (lane == 26) ? 0.f : -INFINITY;
        TmaxL2s = (lane <= 24) ? T[st_o * LS + st_e] * LOG2E : -INFINITY;
    }

    // ---- init state ----
    float* buf0 = &shw[warp][0][0];
    float* buf1 = &shw[warp][1][0];
    #pragma unroll
    for (int i = lane; i < 128; i += 32) buf0[i] = 0.f;
    if (lane == 26) buf0[52] = 1.f;                 // w0 = e_START
    float wn_prev  = (lane == 26) ? 1.f : 0.f;
    float wns_prev = 0.f;

    // ---- 3-deep clamped prefetch ----
    float gd0, gd1, gd2, gs0, gs1, gs2;
    {
        int i1 = min(1, lenm1), i2 = min(2, lenm1);
        gd0 = lg[dld];
        gs0 = lg[sld];
        gd1 = lg[(size_t)i1 * NL + dld];
        gs1 = lg[(size_t)i1 * NL + sld];
        gd2 = lg[(size_t)i2 * NL + dld];
        gs2 = lg[(size_t)i2 * NL + sld];
    }

    int A = 0;   // raw exponent-bit accumulator
    __syncwarp();

#define CRF_STEP(WIN, WOUT, T_CUR)                                            \
    {                                                                         \
        const ulonglong2* wv = reinterpret_cast<const ulonglong2*>(WIN);      \
        ulonglong2 v13 = wv[13];    /* slots 52..55 first: scale path */      \
        unsigned bits = __float_as_uint(f2unpack(v13.x).x);                   \
        float scale = __int_as_float(0x7F000000u - (bits & 0x7F800000u));     \
        A += (int)(bits >> 23);                                               \
        float GD = ex2_approx(__fmaf_rn(gd0 * mD, LOG2E, TmaxL2d)) * scale;   \
        float GS = ex2_approx(__fmaf_rn(gs0, LOG2E, TmaxL2s)) * scale;        \
        float wns = GS * wn_prev;                                             \
        ulonglong2 v[13];                                                     \
        _Pragma("unroll")                                                     \
        for (int j = 0; j < 13; j++) v[j] = wv[j];                            \
        ull a0 = 0, a1 = 0, a2 = 0, a3 = 0;                                   \
        _Pragma("unroll")                                                     \
        for (int j = 0; j < 12; j += 2) {                                     \
            f2fma(a0, E[2 * j],     v[j].x);                                  \
            f2fma(a1, E[2 * j + 1], v[j].y);                                  \
            f2fma(a2, E[2 * j + 2], v[j + 1].x);                              \
            f2fma(a3, E[2 * j + 3], v[j + 1].y);                              \
        }                                                                     \
        f2fma(a0, E[24], v[12].x);                                            \
        f2fma(a1, E[25], v[12].y);                                            \
        f2fma(a2, E[26], v13.x);                                              \
        f2fma(a3, E[27], v13.y);                                              \
        float2 pp = f2unpack(f2add(f2add(a0, a1), f2add(a2, a3)));            \
        float wn = GD * (pp.x + pp.y);                                        \
        reinterpret_cast<float2*>(WOUT)[lane] = make_float2(wn, wns);         \
        wn_prev = wn; wns_prev = wns;                                         \
        gd0 = gd1; gd1 = gd2; gs0 = gs1; gs1 = gs2;                           \
        int tn = min((T_CUR) + 3, lenm1);                                     \
        const float* lgn = lg + (size_t)tn * NL;                              \
        gd2 = lgn[dld];                                                       \
        gs2 = lgn[sld];                                                       \
        __syncwarp();                                                         \
    }

    int t = 0;
    while (t + 2 <= len) {
        CRF_STEP(buf0, buf1, t);
        CRF_STEP(buf1, buf0, t + 1);
        t += 2;
    }
    if (t < len) {
        CRF_STEP(buf0, buf1, t);
    }
#undef CRF_STEP

    // ---- END contraction from registers + warp reduce ----
    float cE_d = (lane <= 26) ? __expf(T[ENDI * LS + st_e] - 100.f) : 0.f;
    float cE_s = (lane <= 24) ? __expf(T[ENDI * LS + st_o] - 100.f) : 0.f;
    float dot = cE_d * wn_prev + cE_s * wns_prev;
    #pragma unroll
    for (int o = 16; o; o >>= 1) dot += __shfl_xor_sync(0xffffffffu, dot, o);
    if (lane == 0) {
        float norm = (float)(A - 127 * len) * LN2 + 100.f + __logf(dot);
        out[b] = -norm;          // crf_gold adds the gold score afterwards
    }
}

extern "C" void kernel_launch(void* const* d_in, const int* in_sizes, int n_in,
                              void* d_out, int out_size)
{
    const float* logits = (const float*)d_in[0];
    const int*   labels = (const int*)d_in[1];
    const int*   lens   = (const int*)d_in[2];
    const float* T      = (const float*)d_in[3];
    float*       out    = (float*)d_out;

    int B = out_size;                       // 256
    int S = in_sizes[1] / B;                // 2048

    crf_fwd <<<B / 2, 64>>>(logits, lens, T, out, S);
    crf_gold<<<B, 256>>>(logits, labels, lens, T, out, S);
}

// round 17
// speedup vs baseline: 1.4080x; 1.0150x over previous
#include <cuda_runtime.h>
#include <math.h>

#define NL 51
#define LS 53
#define STARTI 51
#define ENDI 52
#define LOG2E 1.4426950408889634f
#define LN2   0.6931471805599453f

typedef unsigned long long ull;

__device__ __forceinline__ ull f2pack(float lo, float hi) {
    ull u;
    asm("mov.b64 %0, {%1, %2};" : "=l"(u) : "f"(lo), "f"(hi));
    return u;
}
__device__ __forceinline__ void f2fma(ull& d, ull a, ull b) {
    asm("fma.rn.f32x2 %0, %1, %2, %0;" : "+l"(d) : "l"(a), "l"(b));
}
__device__ __forceinline__ ull f2add(ull a, ull b) {
    ull d;
    asm("add.rn.f32x2 %0, %1, %2;" : "=l"(d) : "l"(a), "l"(b));
    return d;
}
__device__ __forceinline__ float2 f2unpack(ull u) {
    float lo, hi;
    asm("mov.b64 {%0, %1}, %2;" : "=f"(lo), "=f"(hi) : "l"(u));
    return make_float2(lo, hi);
}
__device__ __forceinline__ float ex2_approx(float x) {
    float r;
    asm("ex2.approx.f32 %0, %1;" : "=f"(r) : "f"(x));
    return r;
}

// ---------------------------------------------------------------------------
// Fused-by-CTA kernel. __launch_bounds__(64, 1): minBlocks=1 releases the
// full register budget so the fwd path's E matrix stays in registers
// (R5/R11 fusion failed ONLY because ptxas capped regs at ~96 -> spill).
//   blockIdx <  nFwd : forward recursion, 2 chains (one per warp) — frozen
//                      R6/R16 step structure, byte-identical.
//   blockIdx >= nFwd : gold score for chain (blockIdx - nFwd), 64 threads.
// out[] zeroed by memset; each role contributes one atomicAdd (2 commutative
// addends -> bitwise-deterministic result regardless of execution order).
// fwd CTAs occupy wave 1 (contiguous-modular placement); gold CTAs fill
// later waves and idle SMSPs, overlapping the latency-bound fwd chains.
// ---------------------------------------------------------------------------
__global__ void __launch_bounds__(64, 1) crf_all(const float* __restrict__ logits,
                                                 const int* __restrict__ labels,
                                                 const int* __restrict__ lens,
                                                 const float* __restrict__ T,
                                                 float* __restrict__ out,
                                                 int S, int nFwd)
{
    __shared__ __align__(16) float shw[2][2][64];   // [warp][buf][64]
    __shared__ float red[2];

    const int warp = threadIdx.x >> 5;
    const int lane = threadIdx.x & 31;

    if (blockIdx.x >= nFwd) {
        // =================== gold-score CTA (64 threads, 1 chain) ==========
        const int b = blockIdx.x - nFwd;
        int len = lens[b];
        if (len < 1) len = 1;
        if (len > S) len = S;

        const int*   lab = labels + (size_t)b * S;
        const float* lg  = logits + (size_t)b * S * NL;

        float s = 0.f;
        for (int j = threadIdx.x; j <= len; j += 64) {
            int from = (j == 0)   ? STARTI : lab[j - 1];
            int to   = (j == len) ? ENDI   : lab[j];
            s += __ldg(T + to * LS + from);
            if (j < len) s += __ldg(lg + (size_t)j * NL + to);
        }
        #pragma unroll
        for (int o = 16; o; o >>= 1) s += __shfl_xor_sync(0xffffffffu, s, o);
        if (lane == 0) red[warp] = s;
        __syncthreads();
        if (threadIdx.x == 0) atomicAdd(out + b, red[0] + red[1]);
        return;
    }

    // =================== forward-recursion CTA (frozen R16 body) ===========
    const int b = blockIdx.x * 2 + warp;

    int len = lens[b];
    if (len < 1) len = 1;
    if (len > S) len = S;
    const int lenm1 = len - 1;

    const float* lg = logits + (size_t)b * S * NL;

    // ---- lane roles ----
    const int   st_e = (lane <= 24) ? (2 * lane + 1) : (lane == 25 ? 0 : STARTI);
    const int   st_o = (lane <= 24) ? (2 * lane + 2) : 0;
    const int   dld  = (st_e < NL) ? st_e : 0;      // clamped logit index
    const int   sld  = st_o;
    const float mD   = (lane == 26) ? 0.f : 1.f;    // START uses pad logit: G = 1

    // ---- E row (permuted columns) + constants ----
    ull   E[28];
    float TmaxL2d, TmaxL2s;
    {
        const float* row = T + st_e * LS;
        float m = row[0];
        #pragma unroll
        for (int f = 1; f < LS; f++) m = fmaxf(m, row[f]);
        #pragma unroll
        for (int p = 0; p < 28; p++) {
            int se = (p <= 24) ? (2 * p + 1) : (p == 25 ? 0 : (p == 26 ? STARTI : -1));
            int so = (p <= 24) ? (2 * p + 2) : -1;
            float a = (se >= 0) ? __expf(row[se] - m) : 0.f;
            float c = (so >= 0) ? __expf(row[so] - m) : 0.f;
            E[p] = f2pack(a, c);
        }
        TmaxL2d = (lane <= 25) ? m * LOG2E
                : (lane == 26) ? 0.f : -INFINITY;
        TmaxL2s = (lane <= 24) ? T[st_o * LS + st_e] * LOG2E : -INFINITY;
    }

    // ---- init state ----
    float* buf0 = &shw[warp][0][0];
    float* buf1 = &shw[warp][1][0];
    #pragma unroll
    for (int i = lane; i < 128; i += 32) buf0[i] = 0.f;
    if (lane == 26) buf0[52] = 1.f;                 // w0 = e_START
    float wn_prev  = (lane == 26) ? 1.f : 0.f;
    float wns_prev = 0.f;

    // ---- 3-deep clamped prefetch ----
    float gd0, gd1, gd2, gs0, gs1, gs2;
    {
        int i1 = min(1, lenm1), i2 = min(2, lenm1);
        gd0 = lg[dld];
        gs0 = lg[sld];
        gd1 = lg[(size_t)i1 * NL + dld];
        gs1 = lg[(size_t)i1 * NL + sld];
        gd2 = lg[(size_t)i2 * NL + dld];
        gs2 = lg[(size_t)i2 * NL + sld];
    }

    int A = 0;   // raw exponent-bit accumulator
    __syncwarp();

#define CRF_STEP(WIN, WOUT, T_CUR)                                            \
    {                                                                         \
        const ulonglong2* wv = reinterpret_cast<const ulonglong2*>(WIN);      \
        ulonglong2 v13 = wv[13];    /* slots 52..55 first: scale path */      \
        unsigned bits = __float_as_uint(f2unpack(v13.x).x);                   \
        float scale = __int_as_float(0x7F000000u - (bits & 0x7F800000u));     \
        A += (int)(bits >> 23);                                               \
        float GD = ex2_approx(__fmaf_rn(gd0 * mD, LOG2E, TmaxL2d)) * scale;   \
        float GS = ex2_approx(__fmaf_rn(gs0, LOG2E, TmaxL2s)) * scale;        \
        float wns = GS * wn_prev;                                             \
        ulonglong2 v[13];                                                     \
        _Pragma("unroll")                                                     \
        for (int j = 0; j < 13; j++) v[j] = wv[j];                            \
        ull a0 = 0, a1 = 0, a2 = 0, a3 = 0;                                   \
        _Pragma("unroll")                                                     \
        for (int j = 0; j < 12; j += 2) {                                     \
            f2fma(a0, E[2 * j],     v[j].x);                                  \
            f2fma(a1, E[2 * j + 1], v[j].y);                                  \
            f2fma(a2, E[2 * j + 2], v[j + 1].x);                              \
            f2fma(a3, E[2 * j + 3], v[j + 1].y);                              \
        }                                                                     \
        f2fma(a0, E[24], v[12].x);                                            \
        f2fma(a1, E[25], v[12].y);                                            \
        f2fma(a2, E[26], v13.x);                                              \
        f2fma(a3, E[27], v13.y);                                              \
        float2 pp = f2unpack(f2add(f2add(a0, a1), f2add(a2, a3)));            \
        float wn = GD * (pp.x + pp.y);                                        \
        reinterpret_cast<float2*>(WOUT)[lane] = make_float2(wn, wns);         \
        wn_prev = wn; wns_prev = wns;                                         \
        gd0 = gd1; gd1 = gd2; gs0 = gs1; gs1 = gs2;                           \
        int tn = min((T_CUR) + 3, lenm1);                                     \
        const float* lgn = lg + (size_t)tn * NL;                              \
        gd2 = lgn[dld];                                                       \
        gs2 = lgn[sld];                                                       \
        __syncwarp();                                                         \
    }

    int t = 0;
    while (t + 2 <= len) {
        CRF_STEP(buf0, buf1, t);
        CRF_STEP(buf1, buf0, t + 1);
        t += 2;
    }
    if (t < len) {
        CRF_STEP(buf0, buf1, t);
    }
#undef CRF_STEP

    // ---- END contraction from registers + warp reduce ----
    float cE_d = (lane <= 26) ? __expf(T[ENDI * LS + st_e] - 100.f) : 0.f;
    float cE_s = (lane <= 24) ? __expf(T[ENDI * LS + st_o] - 100.f) : 0.f;
    float dot = cE_d * wn_prev + cE_s * wns_prev;
    #pragma unroll
    for (int o = 16; o; o >>= 1) dot += __shfl_xor_sync(0xffffffffu, dot, o);
    if (lane == 0) {
        float norm = (float)(A - 127 * len) * LN2 + 100.f + __logf(dot);
        atomicAdd(out + b, -norm);      // gold CTA adds the gold score
    }
}

extern "C" void kernel_launch(void* const* d_in, const int* in_sizes, int n_in,
                              void* d_out, int out_size)
{
    const float* logits = (const float*)d_in[0];
    const int*   labels = (const int*)d_in[1];
    const int*   lens   = (const int*)d_in[2];
    const float* T      = (const float*)d_in[3];
    float*       out    = (float*)d_out;

    int B = out_size;                       // 256
    int S = in_sizes[1] / B;                // 2048
    int nFwd = B / 2;                       // 128 fwd CTAs (2 chains each)

    cudaMemsetAsync(out, 0, (size_t)B * sizeof(float), 0);
    crf_all<<<nFwd + B, 64>>>(logits, labels, lens, T, out, S, nFwd);
}